// round 4
// baseline (speedup 1.0000x reference)
#include <cuda_runtime.h>
#include <cuda_bf16.h>
#include <cstdint>

#define NPTS 1024
#define HDIM 32

typedef unsigned long long u64;
typedef unsigned int u32;

// ---------- scratch ----------
__device__ float g_a[NPTS * HDIM];
__device__ float g_c[(NPTS + 2) * HDIM];   // +2 pad rows (prefetch overrun)
__device__ float g_h1[NPTS * HDIM];

// ---------- packed f32x2 helpers ----------
__device__ __forceinline__ u64 f2fma(u64 a, u64 b, u64 c) {
    u64 d;
    asm("fma.rn.f32x2 %0, %1, %2, %3;" : "=l"(d) : "l"(a), "l"(b), "l"(c));
    return d;
}
__device__ __forceinline__ u64 add2(u64 a, u64 b) {
    u64 d;
    asm("add.rn.f32x2 %0, %1, %2;" : "=l"(d) : "l"(a), "l"(b));
    return d;
}
__device__ __forceinline__ u64 pack2(float lo, float hi) {
    u64 r;
    asm("mov.b64 %0, {%1, %2};" : "=l"(r) : "f"(lo), "f"(hi));
    return r;
}
__device__ __forceinline__ void unpack2(float& lo, float& hi, u64 v) {
    asm("mov.b64 {%0, %1}, %2;" : "=f"(lo), "=f"(hi) : "l"(v));
}
__device__ __forceinline__ float hsum2(u64 v) {
    float lo, hi;
    unpack2(lo, hi, v);
    return lo + hi;
}
__device__ __forceinline__ float tanh_hw(float x) {
    float y;
    asm("tanh.approx.f32 %0, %1;" : "=f"(y) : "f"(x));
    return y;
}
__device__ __forceinline__ float sig_hw(float x) {
    return fmaf(tanh_hw(0.5f * x), 0.5f, 0.5f);
}
__device__ __forceinline__ u32 smem_u32(const void* p) {
    u32 a;
    asm("{ .reg .u64 t; cvta.to.shared.u64 t, %1; cvt.u32.u64 %0, t; }"
        : "=r"(a) : "l"(p));
    return a;
}
__device__ __forceinline__ void sts64(u32 addr, u64 v) {
    asm volatile("st.shared.b64 [%0], %1;" :: "r"(addr), "l"(v) : "memory");
}
__device__ __forceinline__ u64 lds64(u32 addr) {
    u64 v;
    asm volatile("ld.shared.b64 %0, [%1];" : "=l"(v) : "r"(addr));
    return v;
}
__device__ __forceinline__ void lds_v2(u64& p0, u64& p1, u32 addr) {
    asm volatile("ld.shared.v2.u64 {%0, %1}, [%2];"
                 : "=l"(p0), "=l"(p1) : "r"(addr));
}

// ---------- precompute: a_i = (Wa-Wb)@x_i + b ; c_j = Wb@x_j ----------
template <int F>
__global__ void __launch_bounds__(256)
pre_kernel(const float* __restrict__ x, const float* __restrict__ w,
           const float* __restrict__ b, float* __restrict__ a,
           float* __restrict__ c) {
    int wq = threadIdx.x >> 5;
    int l = threadIdx.x & 31;
    int i = blockIdx.x * 8 + wq;
    if (i >= NPTS) return;
    float av = b[l];
    float cv = 0.0f;
    const float* wr = w + l * (2 * F);
    const float* xr = x + i * F;
#pragma unroll
    for (int f = 0; f < F; ++f) {
        float xv = xr[f];
        float wa = wr[f];
        float wb = wr[F + f];
        av = fmaf(wa - wb, xv, av);
        cv = fmaf(wb, xv, cv);
    }
    a[i * HDIM + l] = av;
    c[i * HDIM + l] = cv;
}

// ---------- GRU scan: 2 warps per sequence (K split), lane = hidden unit ----
// Warp w owns k in [16w, 16w+16). Both warps FMA their K-half into 3 packed
// partials (lo = Wih@u part, hi = Whh@h part). Warp1 publishes partials via
// smem; warp0 merges, applies the nonlinearity, owns h, and stores the next
// (u, h) pair vector. Two __syncthreads per step.
template <int FUSE_CLF>
__global__ void __launch_bounds__(64, 7)
gru_scan_kernel(const float* __restrict__ a, const float* __restrict__ c,
                const float* __restrict__ wih, const float* __restrict__ whh,
                const float* __restrict__ bih, const float* __restrict__ bhh,
                const float* __restrict__ clf_w, const float* __restrict__ clf_b,
                float* __restrict__ out) {
    __shared__ __align__(16) float2 s_v[2][HDIM];   // [buf][k] (u,h) pairs
    __shared__ __align__(16) u64 s_part[3][HDIM];   // warp1 partials [gate][lane]

    const int w = threadIdx.x >> 5;
    const int l = threadIdx.x & 31;
    const int i = blockIdx.x;

    // This warp's K-half of the interleaved weight pairs: 48 u64.
    u64 Wr[16], Wz[16], Wn[16];
    {
        const int k0 = w * 16;
        const float* pr = wih + (0 * HDIM + l) * HDIM + k0;
        const float* pz = wih + (1 * HDIM + l) * HDIM + k0;
        const float* pn = wih + (2 * HDIM + l) * HDIM + k0;
        const float* qr = whh + (0 * HDIM + l) * HDIM + k0;
        const float* qz = whh + (1 * HDIM + l) * HDIM + k0;
        const float* qn = whh + (2 * HDIM + l) * HDIM + k0;
#pragma unroll
        for (int k = 0; k < 16; ++k) {
            Wr[k] = pack2(pr[k], qr[k]);
            Wz[k] = pack2(pz[k], qz[k]);
            Wn[k] = pack2(pn[k], qn[k]);
        }
    }

    const float b_r = bih[l] + bhh[l];
    const float b_z = bih[HDIM + l] + bhh[HDIM + l];
    const float b_xn = bih[2 * HDIM + l];
    const float b_hn = bhh[2 * HDIM + l];
    const float a_l = a[i * HDIM + l];

    const u32 vbase = smem_u32(&s_v[0][0]);
    const u32 pbase = smem_u32(&s_part[0][0]);
    const u32 vhalf = vbase + (u32)w * 128u;      // this warp's K-half of v
    const u32 pslot = pbase + (u32)l * 8u;        // warp1 partial slots

    float h = 0.0f;
    float c_next;

    // Prologue: seed v[0] = (u_0, h_0=0)
    if (w == 0) {
        float u0 = fmaxf(a_l + c[l], 0.0f);
        sts64(vbase + l * 8u, pack2(u0, 0.0f));
    }
    c_next = c[HDIM + l];   // c[1]
    __syncthreads();

    for (int j = 0; j < NPTS; ++j) {
        // ---- phase A: both warps FMA their K-half of v[j&1] ----
        const u32 va = vhalf + ((j & 1) ? 256u : 0u);
        u64 ar0 = 0ULL, ar1 = 0ULL, az0 = 0ULL, az1 = 0ULL, an0 = 0ULL, an1 = 0ULL;
#pragma unroll
        for (int q = 0; q < 8; ++q) {
            u64 p0, p1;
            lds_v2(p0, p1, va + q * 16);
            ar0 = f2fma(Wr[2 * q], p0, ar0);
            ar1 = f2fma(Wr[2 * q + 1], p1, ar1);
            az0 = f2fma(Wz[2 * q], p0, az0);
            az1 = f2fma(Wz[2 * q + 1], p1, az1);
            an0 = f2fma(Wn[2 * q], p0, an0);
            an1 = f2fma(Wn[2 * q + 1], p1, an1);
        }
        u64 pr = add2(ar0, ar1);
        u64 pz = add2(az0, az1);
        u64 pn = add2(an0, an1);

        if (w == 1) {
            sts64(pslot, pr);
            sts64(pslot + 256u, pz);
            sts64(pslot + 512u, pn);
        }
        __syncthreads();

        // ---- phase B: warp0 merges, nonlinearity, next v ----
        if (w == 0) {
            u64 qr = lds64(pslot);
            u64 qz = lds64(pslot + 256u);
            u64 qn = lds64(pslot + 512u);
            const float r = sig_hw(hsum2(add2(pr, qr)) + b_r);
            const float z = sig_hw(hsum2(add2(pz, qz)) + b_z);
            float xn, hn;
            unpack2(xn, hn, add2(pn, qn));
            const float n = tanh_hw(fmaf(r, hn + b_hn, xn + b_xn));
            h = fmaf(z, h - n, n);

            const float u = fmaxf(a_l + c_next, 0.0f);   // u_{j+1}
            sts64(vbase + ((j & 1) ? 0u : 256u) + l * 8u, pack2(u, h));
        }
        c_next = c[(j + 2) * HDIM + l];   // rows NPTS, NPTS+1 are zero pad
        __syncthreads();
    }

    if (w == 0) {
        if (FUSE_CLF) {
            s_v[0][l].x = h;
            __syncwarp();
            if (l < 3) {
                float acc = clf_b[l];
                const float* cw = clf_w + l * HDIM;
#pragma unroll
                for (int hh = 0; hh < HDIM; ++hh)
                    acc = fmaf(cw[hh], s_v[0][hh].x, acc);
                out[i * 3 + l] = acc;
            }
        } else {
            out[i * HDIM + l] = h;
        }
    }
}

extern "C" void kernel_launch(void* const* d_in, const int* in_sizes, int n_in,
                              void* d_out, int out_size) {
    const float* x        = (const float*)d_in[0];
    const float* proj1_w  = (const float*)d_in[1];
    const float* proj1_b  = (const float*)d_in[2];
    const float* gru1_wih = (const float*)d_in[3];
    const float* gru1_whh = (const float*)d_in[4];
    const float* gru1_bih = (const float*)d_in[5];
    const float* gru1_bhh = (const float*)d_in[6];
    const float* proj2_w  = (const float*)d_in[7];
    const float* proj2_b  = (const float*)d_in[8];
    const float* gru2_wih = (const float*)d_in[9];
    const float* gru2_whh = (const float*)d_in[10];
    const float* gru2_bih = (const float*)d_in[11];
    const float* gru2_bhh = (const float*)d_in[12];
    const float* clf_w    = (const float*)d_in[13];
    const float* clf_b    = (const float*)d_in[14];
    float* out = (float*)d_out;

    float *pa, *pc, *ph1;
    cudaGetSymbolAddress((void**)&pa, g_a);
    cudaGetSymbolAddress((void**)&pc, g_c);
    cudaGetSymbolAddress((void**)&ph1, g_h1);

    pre_kernel<16><<<128, 256>>>(x, proj1_w, proj1_b, pa, pc);
    gru_scan_kernel<0><<<1024, 64>>>(pa, pc, gru1_wih, gru1_whh, gru1_bih,
                                     gru1_bhh, nullptr, nullptr, ph1);
    pre_kernel<32><<<128, 256>>>(ph1, proj2_w, proj2_b, pa, pc);
    gru_scan_kernel<1><<<1024, 64>>>(pa, pc, gru2_wih, gru2_whh, gru2_bih,
                                     gru2_bhh, clf_w, clf_b, out);
}

// round 5
// speedup vs baseline: 1.3396x; 1.3396x over previous
#include <cuda_runtime.h>
#include <cuda_bf16.h>
#include <cstdint>

#define NPTS 1024
#define HDIM 32

typedef unsigned long long u64;
typedef unsigned int u32;

// ---------- scratch ----------
__device__ float g_a[NPTS * HDIM];
__device__ float g_c[(NPTS + 4) * HDIM];   // +4 zero pad rows (prefetch overrun)
__device__ float g_h1[NPTS * HDIM];

// ---------- packed f32x2 helpers ----------
__device__ __forceinline__ u64 f2fma(u64 a, u64 b, u64 c) {
    u64 d;
    asm("fma.rn.f32x2 %0, %1, %2, %3;" : "=l"(d) : "l"(a), "l"(b), "l"(c));
    return d;
}
__device__ __forceinline__ u64 add2(u64 a, u64 b) {
    u64 d;
    asm("add.rn.f32x2 %0, %1, %2;" : "=l"(d) : "l"(a), "l"(b));
    return d;
}
__device__ __forceinline__ u64 pack2(float lo, float hi) {
    u64 r;
    asm("mov.b64 %0, {%1, %2};" : "=l"(r) : "f"(lo), "f"(hi));
    return r;
}
__device__ __forceinline__ void unpack2(float& lo, float& hi, u64 v) {
    asm("mov.b64 {%0, %1}, %2;" : "=f"(lo), "=f"(hi) : "l"(v));
}
__device__ __forceinline__ float hsum2(u64 v) {
    float lo, hi;
    unpack2(lo, hi, v);
    return lo + hi;
}
__device__ __forceinline__ float tanh_hw(float x) {
    float y;
    asm("tanh.approx.f32 %0, %1;" : "=f"(y) : "f"(x));
    return y;
}
__device__ __forceinline__ float sig_hw(float x) {
    return fmaf(tanh_hw(0.5f * x), 0.5f, 0.5f);
}
__device__ __forceinline__ u32 smem_u32(const void* p) {
    u32 a;
    asm("{ .reg .u64 t; cvta.to.shared.u64 t, %1; cvt.u32.u64 %0, t; }"
        : "=r"(a) : "l"(p));
    return a;
}
__device__ __forceinline__ void sts32(u32 addr, float v) {
    asm volatile("st.shared.b32 [%0], %1;" :: "r"(addr), "f"(v) : "memory");
}
__device__ __forceinline__ void lds_v2(u64& p0, u64& p1, u32 addr) {
    asm volatile("ld.shared.v2.u64 {%0, %1}, [%2];"
                 : "=l"(p0), "=l"(p1) : "r"(addr));
}

// ---------- precompute: a_i = (Wa-Wb)@x_i + b ; c_j = Wb@x_j ----------
template <int F>
__global__ void __launch_bounds__(256)
pre_kernel(const float* __restrict__ x, const float* __restrict__ w,
           const float* __restrict__ b, float* __restrict__ a,
           float* __restrict__ c) {
    int wq = threadIdx.x >> 5;
    int l = threadIdx.x & 31;
    int i = blockIdx.x * 8 + wq;
    if (i >= NPTS) return;
    float av = b[l];
    float cv = 0.0f;
    const float* wr = w + l * (2 * F);
    const float* xr = x + i * F;
#pragma unroll
    for (int f = 0; f < F; ++f) {
        float xv = xr[f];
        float wa = wr[f];
        float wb = wr[F + f];
        av = fmaf(wa - wb, xv, av);
        cv = fmaf(wb, xv, cv);
    }
    a[i * HDIM + l] = av;
    c[i * HDIM + l] = cv;
}

// ---------- GRU scan: 1 warp per sequence, software-pipelined ----------
// Iteration j computes:  hg_j = Whh @ h_{j-1}   (dependent half)
//                        xg_{j+1} = Wih @ u_{j+1} (independent half, hides latency)
// then the tail uses xg_j (carried from last iteration) + hg_j.
// Adjacent-k f32x2 packing: weight rows load as natural u64 pairs.
template <int FUSE_CLF>
__global__ void __launch_bounds__(64, 2)
gru_scan_kernel(const float* __restrict__ a, const float* __restrict__ c,
                const float* __restrict__ wih, const float* __restrict__ whh,
                const float* __restrict__ bih, const float* __restrict__ bhh,
                const float* __restrict__ clf_w, const float* __restrict__ clf_b,
                float* __restrict__ out) {
    __shared__ __align__(16) float s_u[2][2][HDIM];  // [warp][buf][k]
    __shared__ __align__(16) float s_h[2][2][HDIM];

    const int w = threadIdx.x >> 5;
    const int l = threadIdx.x & 31;
    const int i = blockIdx.x * 2 + w;

    // Weight rows as adjacent-k u64 pairs (96 u64).
    u64 Wxr[16], Wxz[16], Wxn[16], Whr[16], Whz[16], Whn[16];
    {
        const u64* pxr = (const u64*)(wih + (0 * HDIM + l) * HDIM);
        const u64* pxz = (const u64*)(wih + (1 * HDIM + l) * HDIM);
        const u64* pxn = (const u64*)(wih + (2 * HDIM + l) * HDIM);
        const u64* phr = (const u64*)(whh + (0 * HDIM + l) * HDIM);
        const u64* phz = (const u64*)(whh + (1 * HDIM + l) * HDIM);
        const u64* phn = (const u64*)(whh + (2 * HDIM + l) * HDIM);
#pragma unroll
        for (int q = 0; q < 16; ++q) {
            Wxr[q] = pxr[q];
            Wxz[q] = pxz[q];
            Wxn[q] = pxn[q];
            Whr[q] = phr[q];
            Whz[q] = phz[q];
            Whn[q] = phn[q];
        }
    }

    const u64 init_r = pack2(bih[l] + bhh[l], 0.0f);
    const u64 init_z = pack2(bih[HDIM + l] + bhh[HDIM + l], 0.0f);
    const u64 init_n = pack2(bih[2 * HDIM + l], 0.0f);
    const float b_hn = bhh[2 * HDIM + l];
    const float a_l = a[i * HDIM + l];

    const u32 ub = smem_u32(&s_u[w][0][0]);
    const u32 hb = smem_u32(&s_h[w][0][0]);

    float h = 0.0f;

    // ---- prologue: xg_0 = Wih @ u_0 + bias (use buf1) ----
    u64 xg_r, xg_z, xg_n;
    {
        float u0 = fmaxf(a_l + c[l], 0.0f);
        sts32(ub + 128u + l * 4u, u0);
        __syncwarp();
        u64 a0 = init_r, a1 = 0ULL, b0 = init_z, b1 = 0ULL, c0 = init_n, c1 = 0ULL;
#pragma unroll
        for (int q = 0; q < 8; ++q) {
            u64 u0p, u1p;
            lds_v2(u0p, u1p, ub + 128u + q * 16u);
            a0 = f2fma(Wxr[2 * q], u0p, a0);
            a1 = f2fma(Wxr[2 * q + 1], u1p, a1);
            b0 = f2fma(Wxz[2 * q], u0p, b0);
            b1 = f2fma(Wxz[2 * q + 1], u1p, b1);
            c0 = f2fma(Wxn[2 * q], u0p, c0);
            c1 = f2fma(Wxn[2 * q + 1], u1p, c1);
        }
        xg_r = add2(a0, a1);
        xg_z = add2(b0, b1);
        xg_n = add2(c0, c1);
    }

    float c_next = c[1 * HDIM + l];   // c[j+1] for j=0
    float c_next2 = c[2 * HDIM + l];

    for (int j = 0; j < NPTS; ++j) {
        const u32 boff = (j & 1) ? 128u : 0u;

        // publish h_{j-1} and u_{j+1}
        const float u_next = fmaxf(a_l + c_next, 0.0f);
        c_next = c_next2;
        c_next2 = c[(j + 3) * HDIM + l];   // rows >= NPTS are zero pad
        sts32(hb + boff + l * 4u, h);
        sts32(ub + boff + l * 4u, u_next);
        __syncwarp();

        // dependent (hg_j) and independent (xg_{j+1}) halves, interleaved
        u64 hr0 = 0ULL, hr1 = 0ULL, hz0 = 0ULL, hz1 = 0ULL, hn0 = 0ULL, hn1 = 0ULL;
        u64 xr0 = init_r, xr1 = 0ULL, xz0 = init_z, xz1 = 0ULL, xn0 = init_n, xn1 = 0ULL;
#pragma unroll
        for (int q = 0; q < 8; ++q) {
            u64 h0p, h1p, u0p, u1p;
            lds_v2(h0p, h1p, hb + boff + q * 16u);
            lds_v2(u0p, u1p, ub + boff + q * 16u);
            hr0 = f2fma(Whr[2 * q], h0p, hr0);
            hr1 = f2fma(Whr[2 * q + 1], h1p, hr1);
            xr0 = f2fma(Wxr[2 * q], u0p, xr0);
            xr1 = f2fma(Wxr[2 * q + 1], u1p, xr1);
            hz0 = f2fma(Whz[2 * q], h0p, hz0);
            hz1 = f2fma(Whz[2 * q + 1], h1p, hz1);
            xz0 = f2fma(Wxz[2 * q], u0p, xz0);
            xz1 = f2fma(Wxz[2 * q + 1], u1p, xz1);
            hn0 = f2fma(Whn[2 * q], h0p, hn0);
            hn1 = f2fma(Whn[2 * q + 1], h1p, hn1);
            xn0 = f2fma(Wxn[2 * q], u0p, xn0);
            xn1 = f2fma(Wxn[2 * q + 1], u1p, xn1);
        }

        // tail for step j (uses carried xg_j + fresh hg_j)
        const float r = sig_hw(hsum2(add2(xg_r, add2(hr0, hr1))));
        const float z = sig_hw(hsum2(add2(xg_z, add2(hz0, hz1))));
        const float xn_v = hsum2(xg_n);
        const float hn_v = hsum2(add2(hn0, hn1)) + b_hn;
        const float n = tanh_hw(fmaf(r, hn_v, xn_v));
        h = fmaf(z, h - n, n);

        // carry xg_{j+1}
        xg_r = add2(xr0, xr1);
        xg_z = add2(xz0, xz1);
        xg_n = add2(xn0, xn1);
    }

    if (FUSE_CLF) {
        sts32(hb + l * 4u, h);
        __syncwarp();
        if (l < 3) {
            float acc = clf_b[l];
            const float* cw = clf_w + l * HDIM;
#pragma unroll
            for (int hh = 0; hh < HDIM; ++hh)
                acc = fmaf(cw[hh], s_h[w][0][hh], acc);
            out[i * 3 + l] = acc;
        }
    } else {
        out[i * HDIM + l] = h;
    }
}

extern "C" void kernel_launch(void* const* d_in, const int* in_sizes, int n_in,
                              void* d_out, int out_size) {
    const float* x        = (const float*)d_in[0];
    const float* proj1_w  = (const float*)d_in[1];
    const float* proj1_b  = (const float*)d_in[2];
    const float* gru1_wih = (const float*)d_in[3];
    const float* gru1_whh = (const float*)d_in[4];
    const float* gru1_bih = (const float*)d_in[5];
    const float* gru1_bhh = (const float*)d_in[6];
    const float* proj2_w  = (const float*)d_in[7];
    const float* proj2_b  = (const float*)d_in[8];
    const float* gru2_wih = (const float*)d_in[9];
    const float* gru2_whh = (const float*)d_in[10];
    const float* gru2_bih = (const float*)d_in[11];
    const float* gru2_bhh = (const float*)d_in[12];
    const float* clf_w    = (const float*)d_in[13];
    const float* clf_b    = (const float*)d_in[14];
    float* out = (float*)d_out;

    float *pa, *pc, *ph1;
    cudaGetSymbolAddress((void**)&pa, g_a);
    cudaGetSymbolAddress((void**)&pc, g_c);
    cudaGetSymbolAddress((void**)&ph1, g_h1);

    pre_kernel<16><<<128, 256>>>(x, proj1_w, proj1_b, pa, pc);
    gru_scan_kernel<0><<<512, 64>>>(pa, pc, gru1_wih, gru1_whh, gru1_bih,
                                    gru1_bhh, nullptr, nullptr, ph1);
    pre_kernel<32><<<128, 256>>>(ph1, proj2_w, proj2_b, pa, pc);
    gru_scan_kernel<1><<<512, 64>>>(pa, pc, gru2_wih, gru2_whh, gru2_bih,
                                    gru2_bhh, clf_w, clf_b, out);
}